// round 15
// baseline (speedup 1.0000x reference)
#include <cuda_runtime.h>
#include <cuda_bf16.h>
#include <cfloat>
#include <climits>
#include <cstdint>

// Problem constants
#define B_ 32768
#define D_ 512
#define L_ 4
#define K_ 1024

// Candidate margin (score units). Screened-score error is bf16-GEMM noise only
// (sigma ~0.014); 0.15 ~ 10 sigma. Single final candidate => provably the
// reference argmin; otherwise tiered exact rescore.
#define MARGIN 0.15f
#define MAXCAND 12
// fp32-tier ambiguity guard: pairwise |S_f32 - S_ref| bound ~2.5e-4; 6e-4 is
// comfortably above it, so fp32 gap >= guard proves the reference ordering.
#define FP32_GUARD 6e-4f

// ---------------- scratch (__device__ globals; no allocations allowed) -----------
__device__ float          g_residual[(size_t)B_ * D_];   // fp32 residual, 64 MB
__device__ __nv_bfloat16  g_rb[(size_t)B_ * D_];         // bf16 residual (GEMM A), 32 MB
__device__ __nv_bfloat16  g_cbh[(size_t)L_ * K_ * D_];   // bf16 codebooks, 4 MB
__device__ float          g_c2[L_ * K_];
__device__ int            g_ccnt[B_];
__device__ int            g_cand[B_][MAXCAND];
__device__ float          g_rowss[L_ * B_];

__device__ __forceinline__ uint32_t smem_u32(const void* p) {
    uint32_t a;
    asm("{ .reg .u64 t; cvta.to.shared.u64 t, %1; cvt.u32.u64 %0, t; }" : "=r"(a) : "l"(p));
    return a;
}
// order-preserving float <-> uint map (atomicMin on scores, incl. negatives)
__device__ __forceinline__ unsigned fkey(float f) {
    unsigned u = __float_as_uint(f);
    return (u & 0x80000000u) ? ~u : (u | 0x80000000u);
}
__device__ __forceinline__ float fdec(unsigned k) {
    unsigned u = (k & 0x80000000u) ? (k ^ 0x80000000u) : ~k;
    return __uint_as_float(u);
}

// ---------------- fused codebook prep: bf16 convert + ||c||^2 --------------------
// One warp per codeword: single 8 MB read serves both outputs.
// c2 fp64-accumulated -> correctly-rounded fp32 (order-independent at fp32).
__global__ void convc2_kernel(const float* __restrict__ cb) {
    int g = blockIdx.x * blockDim.x + threadIdx.x;
    int w = g >> 5, lane = g & 31;
    const float* row = cb + (size_t)w * D_;
    // 16 contiguous floats per lane
    float4 v[4];
    #pragma unroll
    for (int q = 0; q < 4; q++)
        v[q] = reinterpret_cast<const float4*>(row)[lane * 4 + q];
    double s = 0.0;
    __nv_bfloat162 h[8];
    #pragma unroll
    for (int q = 0; q < 4; q++) {
        h[q * 2 + 0] = __floats2bfloat162_rn(v[q].x, v[q].y);
        h[q * 2 + 1] = __floats2bfloat162_rn(v[q].z, v[q].w);
        s = fma((double)v[q].x, (double)v[q].x, s);
        s = fma((double)v[q].y, (double)v[q].y, s);
        s = fma((double)v[q].z, (double)v[q].z, s);
        s = fma((double)v[q].w, (double)v[q].w, s);
    }
    __nv_bfloat16* dst = g_cbh + (size_t)w * D_ + lane * 16;
    *reinterpret_cast<uint4*>(dst)     = *reinterpret_cast<uint4*>(&h[0]);
    *reinterpret_cast<uint4*>(dst + 8) = *reinterpret_cast<uint4*>(&h[4]);
    #pragma unroll
    for (int o = 16; o; o >>= 1) s += __shfl_xor_sync(0xffffffffu, s, o);
    if (!lane) g_c2[w] = (float)s;
}

// ---------------- bf16 MMA GEMM + fused min/candidate epilogue -------------------
// Per CTA: 64 rows x all 1024 codes, K=512. 256 threads, warp tile 32x32,
// 2 CTA/SM. 3-stage B pipeline (2 chunks in flight during compute).
// Level 0 stages A directly from z (inline fp32->bf16 convert).
#define SM_A     0
#define SM_B     65536
#define SM_BBUF  16384
#define SM_TOTAL (65536 + 3 * 16384)

__device__ __forceinline__ void ldsm_x4(uint32_t* r, uint32_t addr) {
    asm volatile("ldmatrix.sync.aligned.m8n8.x4.shared.b16 {%0,%1,%2,%3}, [%4];"
        : "=r"(r[0]), "=r"(r[1]), "=r"(r[2]), "=r"(r[3]) : "r"(addr));
}
__device__ __forceinline__ void mma16816(float* c, const uint32_t* a, uint32_t b0, uint32_t b1) {
    asm volatile("mma.sync.aligned.m16n8k16.row.col.f32.bf16.bf16.f32 "
        "{%0,%1,%2,%3}, {%4,%5,%6,%7}, {%8,%9}, {%0,%1,%2,%3};"
        : "+f"(c[0]), "+f"(c[1]), "+f"(c[2]), "+f"(c[3])
        : "r"(a[0]), "r"(a[1]), "r"(a[2]), "r"(a[3]), "r"(b0), "r"(b1));
}

__global__ __launch_bounds__(256, 2) void gemm_kernel(const float* __restrict__ z, int level) {
    extern __shared__ char smem[];
    __shared__ unsigned bestKey[64];
    __shared__ int   ccnt[64];
    __shared__ int   candI[64][MAXCAND];
    __shared__ float candS[64][MAXCAND];

    const int tid = threadIdx.x, wid = tid >> 5, lane = tid & 31;
    const int m0 = blockIdx.x * 64;
    const __nv_bfloat16* Bsrc = g_cbh + (size_t)level * K_ * D_;
    const float* c2l = g_c2 + level * K_;
    const uint32_t sb = smem_u32(smem);

    if (tid < 64) { bestKey[tid] = 0xFFFFFFFFu; ccnt[tid] = 0; }

    // Stage A: 64 rows x 512 bf16, XOR-swizzled 16B chunks.
    if (level == 0) {
        // Read z directly, convert inline (no g_rb round-trip for level 0).
        #pragma unroll
        for (int i = 0; i < 16; i++) {
            int q = tid + i * 256;
            int m = q >> 6, c = q & 63;
            const float* zp = z + (size_t)(m0 + m) * D_ + c * 8;
            float4 a = *reinterpret_cast<const float4*>(zp);
            float4 b = *reinterpret_cast<const float4*>(zp + 4);
            __nv_bfloat162 h[4] = { __floats2bfloat162_rn(a.x, a.y),
                                    __floats2bfloat162_rn(a.z, a.w),
                                    __floats2bfloat162_rn(b.x, b.y),
                                    __floats2bfloat162_rn(b.z, b.w) };
            *reinterpret_cast<uint4*>(smem + SM_A + m * 1024 + ((c ^ (m & 7)) * 16)) =
                *reinterpret_cast<uint4*>(h);
        }
        asm volatile("cp.async.commit_group;");   // empty group: keeps group count uniform
    } else {
        #pragma unroll
        for (int i = 0; i < 16; i++) {
            int q = tid + i * 256;
            int m = q >> 6, c = q & 63;
            uint32_t dst = sb + SM_A + m * 1024 + ((c ^ (m & 7)) * 16);
            const void* g = g_rb + (size_t)(m0 + m) * D_ + c * 8;
            asm volatile("cp.async.cg.shared.global [%0], [%1], 16;" :: "r"(dst), "l"(g));
        }
        asm volatile("cp.async.commit_group;");
    }

    // B chunk ci in 0..63: nt = ci>>3 (128-col tile), kc = ci&7 (64-k slab).
    #define LOAD_B_CHUNK(ci, buf) do {                                               \
        int _nt = (ci) >> 3, _kc = (ci) & 7;                                         \
        const __nv_bfloat16* _src = Bsrc + (size_t)(_nt * 128) * D_ + _kc * 64;      \
        _Pragma("unroll")                                                            \
        for (int _i = 0; _i < 4; _i++) {                                             \
            int _q = tid + _i * 256;                                                 \
            int _n = _q >> 3, _c = _q & 7;                                           \
            uint32_t _dst = sb + SM_B + (buf) * SM_BBUF + _n * 128 +                 \
                            ((_c ^ (_n & 7)) * 16);                                  \
            const void* _g = _src + (size_t)_n * D_ + _c * 8;                        \
            asm volatile("cp.async.cg.shared.global [%0], [%1], 16;"                 \
                         :: "r"(_dst), "l"(_g));                                     \
        }                                                                            \
        asm volatile("cp.async.commit_group;");                                      \
    } while (0)

    const int wm = wid & 1, wn = wid >> 1;   // warp tile: rows wm*32..+31, cols wn*32..+31
    const int lr = lane & 7;
    const int lh = (lane >> 3) & 1;
    const int lk = lane >> 4;

    LOAD_B_CHUNK(0, 0);
    LOAD_B_CHUNK(1, 1);

    float acc[2][4][4];

    for (int ci = 0; ci < 64; ci++) {
        const int buf = ci % 3;
        // Ensure chunk ci has landed; keep chunk ci+1 in flight.
        if (ci + 1 < 64) { asm volatile("cp.async.wait_group 1;"); }
        else             { asm volatile("cp.async.wait_group 0;"); }
        __syncthreads();
        // Issue chunk ci+2 into buffer (ci+2)%3 (last read in iteration ci-1,
        // whose reads completed before the barrier above).
        if (ci + 2 < 64) LOAD_B_CHUNK(ci + 2, (ci + 2) % 3);

        const int nt = ci >> 3, kc = ci & 7;

        if (kc == 0) {
            #pragma unroll
            for (int mt = 0; mt < 2; mt++)
                #pragma unroll
                for (int nti = 0; nti < 4; nti++)
                    #pragma unroll
                    for (int q = 0; q < 4; q++) acc[mt][nti][q] = 0.f;
        }

        #pragma unroll
        for (int ks = 0; ks < 4; ks++) {
            uint32_t a[2][4];
            #pragma unroll
            for (int mt = 0; mt < 2; mt++) {
                int m = wm * 32 + mt * 16 + lh * 8 + lr;
                int ch = kc * 8 + ks * 2 + lk;
                uint32_t addr = sb + SM_A + m * 1024 + ((ch ^ (m & 7)) * 16);
                ldsm_x4(a[mt], addr);
            }
            uint32_t b[2][4];
            #pragma unroll
            for (int p = 0; p < 2; p++) {
                int n = wn * 32 + p * 16 + lk * 8 + lr;
                int ch = ks * 2 + lh;
                uint32_t addr = sb + SM_B + buf * SM_BBUF + n * 128 + ((ch ^ (n & 7)) * 16);
                ldsm_x4(b[p], addr);
            }
            #pragma unroll
            for (int mt = 0; mt < 2; mt++)
                #pragma unroll
                for (int nti = 0; nti < 4; nti++)
                    mma16816(acc[mt][nti], a[mt],
                             b[nti >> 1][(nti & 1) * 2 + 0],
                             b[nti >> 1][(nti & 1) * 2 + 1]);
        }

        if (kc == 7) {
            // ---- epilogue for this 128-col tile ----
            // pass 1: per-row running min (ordered-uint atomicMin)
            #pragma unroll
            for (int mt = 0; mt < 2; mt++) {
                #pragma unroll
                for (int h = 0; h < 2; h++) {
                    int row = wm * 32 + mt * 16 + h * 8 + (lane >> 2);
                    float lmin = FLT_MAX;
                    #pragma unroll
                    for (int nti = 0; nti < 4; nti++) {
                        int col = nt * 128 + wn * 32 + nti * 8 + (lane & 3) * 2;
                        float2 cv = *reinterpret_cast<const float2*>(c2l + col);
                        float s0 = fmaf(-2.f, acc[mt][nti][h * 2 + 0], cv.x);
                        float s1 = fmaf(-2.f, acc[mt][nti][h * 2 + 1], cv.y);
                        lmin = fminf(lmin, fminf(s0, s1));
                    }
                    atomicMin(&bestKey[row], fkey(lmin));
                }
            }
            __syncthreads();
            // pass 2: candidates vs (running min + MARGIN) [superset of final set]
            #pragma unroll
            for (int mt = 0; mt < 2; mt++) {
                #pragma unroll
                for (int h = 0; h < 2; h++) {
                    int row = wm * 32 + mt * 16 + h * 8 + (lane >> 2);
                    float thr = fdec(bestKey[row]) + MARGIN;
                    #pragma unroll
                    for (int nti = 0; nti < 4; nti++) {
                        int col = nt * 128 + wn * 32 + nti * 8 + (lane & 3) * 2;
                        float2 cv = *reinterpret_cast<const float2*>(c2l + col);
                        float s0 = fmaf(-2.f, acc[mt][nti][h * 2 + 0], cv.x);
                        float s1 = fmaf(-2.f, acc[mt][nti][h * 2 + 1], cv.y);
                        if (s0 <= thr) {
                            int p = atomicAdd(&ccnt[row], 1);
                            if (p < MAXCAND) { candI[row][p] = col; candS[row][p] = s0; }
                        }
                        if (s1 <= thr) {
                            int p = atomicAdd(&ccnt[row], 1);
                            if (p < MAXCAND) { candI[row][p] = col + 1; candS[row][p] = s1; }
                        }
                    }
                }
            }
        }
    }
    #undef LOAD_B_CHUNK
    __syncthreads();

    // Final per-row filter & writeout (one thread per row).
    if (tid < 64) {
        int b = m0 + tid;
        int c = ccnt[tid];
        if (c > MAXCAND) {
            g_ccnt[b] = 999;                       // overflow: full rescan in resolve
        } else {
            float thr = fdec(bestKey[tid]) + MARGIN;
            int m = 0;
            for (int i = 0; i < c; i++)
                if (candS[tid][i] <= thr) g_cand[b][m++] = candI[tid][i];
            g_ccnt[b] = m;                          // m >= 1 always (min itself)
        }
    }
}

// ---------------- candidate resolve + tiered exact rescore + update --------------
// One warp per row (fused — proven faster than split at this kernel size).
// n==1 => provably correct winner. Else tier-1: fp32 exact-input rescore; if
// its top-2 gap >= FP32_GUARD the winner provably matches the reference
// argmin. Residue -> tier-2: fp64 dot + the reference's fp32 rounding chain
// (lowest-index ties). Then residual update, level vec, bf16 mirror (levels
// 0-2), per-row sumsq, and at level 3 quantized = z - residual.
__global__ __launch_bounds__(256) void argmin_update_kernel(const float* __restrict__ z,
                                                            const float* __restrict__ cb,
                                                            float* __restrict__ lv_base,
                                                            float* __restrict__ outq,
                                                            int level) {
    const int tid = threadIdx.x, wid = tid >> 5, lane = tid & 31;
    const int b = blockIdx.x * 8 + wid;
    const float* prevres = level ? g_residual : z;
    const float* rrow = prevres + (size_t)b * D_;
    const float* cbl = cb + (size_t)level * K_ * D_;
    const float* c2l = g_c2 + level * K_;

    int n = g_ccnt[b];
    int idx;
    if (n == 1) {
        idx = g_cand[b][0];
    } else {
        float rres[16];
        #pragma unroll
        for (int j = 0; j < 16; j++) rres[j] = rrow[j * 32 + lane];
        const bool full = (n > MAXCAND);
        const int cnt = full ? K_ : n;

        // ---- tier 1: fp32 exact-input rescore, track top-2 ----
        float bestS = FLT_MAX, secondS = FLT_MAX; int bi = INT_MAX;
        for (int t = 0; t < cnt; t++) {
            int k = full ? t : g_cand[b][t];
            const float* crow = cbl + (size_t)k * D_;
            float dp0 = 0.f, dp1 = 0.f;
            #pragma unroll
            for (int j = 0; j < 16; j += 2) {
                dp0 = fmaf(rres[j],     crow[j * 32 + lane],       dp0);
                dp1 = fmaf(rres[j + 1], crow[(j + 1) * 32 + lane], dp1);
            }
            float dp = dp0 + dp1;
            #pragma unroll
            for (int o = 16; o; o >>= 1) dp += __shfl_xor_sync(0xffffffffu, dp, o);
            float S = fmaf(-2.f, dp, __ldg(c2l + k));
            if (S < bestS || (S == bestS && k < bi)) {
                secondS = bestS; bestS = S; bi = k;
            } else if (S < secondS) {
                secondS = S;
            }
        }
        idx = bi;

        // ---- tier 2: ambiguous -> fp64 + reference fp32 rounding chain ----
        if (secondS - bestS < FP32_GUARD) {
            double rd[16]; double r2 = 0.0;
            #pragma unroll
            for (int j = 0; j < 16; j++) {
                double v = (double)rres[j];
                rd[j] = v; r2 = fma(v, v, r2);
            }
            #pragma unroll
            for (int o = 16; o; o >>= 1) r2 += __shfl_xor_sync(0xffffffffu, r2, o);
            float r2f = (float)r2;

            float bS = FLT_MAX; int bk = INT_MAX;
            for (int t = 0; t < cnt; t++) {
                int k = full ? t : g_cand[b][t];
                const float* crow = cbl + (size_t)k * D_;
                double dp0 = 0.0, dp1 = 0.0;
                #pragma unroll
                for (int j = 0; j < 16; j += 2) {
                    dp0 = fma(rd[j],     (double)crow[j * 32 + lane],       dp0);
                    dp1 = fma(rd[j + 1], (double)crow[(j + 1) * 32 + lane], dp1);
                }
                double dp = dp0 + dp1;
                #pragma unroll
                for (int o = 16; o; o >>= 1) dp += __shfl_xor_sync(0xffffffffu, dp, o);
                float S = __fadd_rn(__fsub_rn(r2f, __fmul_rn(2.0f, (float)dp)),
                                    __ldg(c2l + k));
                if (S < bS || (S == bS && k < bk)) { bS = S; bk = k; }
            }
            idx = bk;
        }
    }

    // ---- update phase ----
    const float4* c  = reinterpret_cast<const float4*>(cbl + (size_t)idx * D_);
    const float4* r  = reinterpret_cast<const float4*>(rrow);
    float4* ro = reinterpret_cast<float4*>(g_residual + (size_t)b * D_);
    float4* lo = reinterpret_cast<float4*>(lv_base + (size_t)level * B_ * D_ + (size_t)b * D_);
    const float4* zv = reinterpret_cast<const float4*>(z + (size_t)b * D_);
    float4* oq = reinterpret_cast<float4*>(outq + (size_t)b * D_);
    float ss = 0.f;
    #pragma unroll
    for (int d = lane; d < D_ / 4; d += 32) {
        float4 rv = r[d], cv = c[d];
        float4 nv = make_float4(rv.x - cv.x, rv.y - cv.y, rv.z - cv.z, rv.w - cv.w);
        lo[d] = cv;
        if (level < 3) {
            ro[d] = nv;
            __nv_bfloat162 h0 = __floats2bfloat162_rn(nv.x, nv.y);
            __nv_bfloat162 h1 = __floats2bfloat162_rn(nv.z, nv.w);
            uint2 pk = make_uint2(*reinterpret_cast<uint32_t*>(&h0),
                                  *reinterpret_cast<uint32_t*>(&h1));
            *reinterpret_cast<uint2*>(g_rb + (size_t)b * D_ + d * 4) = pk;
        } else {
            float4 zq = zv[d];
            oq[d] = make_float4(zq.x - nv.x, zq.y - nv.y, zq.z - nv.z, zq.w - nv.w);
        }
        ss = fmaf(nv.x, nv.x, fmaf(nv.y, nv.y, fmaf(nv.z, nv.z, fmaf(nv.w, nv.w, ss))));
    }
    #pragma unroll
    for (int o = 16; o; o >>= 1) ss += __shfl_xor_sync(0xffffffffu, ss, o);
    if (!lane) g_rowss[level * B_ + b] = ss;
}

// ---------------- loss: levels reduced in parallel (deterministic tree) ----------
__global__ __launch_bounds__(1024) void loss_kernel(float* __restrict__ out) {
    __shared__ double sh[1024];
    __shared__ float means[L_];
    const int t = threadIdx.x;
    const int l = t >> 8, u = t & 255;
    double s = 0.0;
    #pragma unroll 8
    for (int i = u; i < B_; i += 256) s += (double)g_rowss[l * B_ + i];
    sh[t] = s; __syncthreads();
    for (int o = 128; o; o >>= 1) {
        if (u < o) sh[t] += sh[t + o];
        __syncthreads();
    }
    if (u == 0) means[l] = (float)(sh[t] / ((double)B_ * (double)D_));
    __syncthreads();
    if (t == 0) {
        float loss = 0.f;
        for (int lv = 0; lv < L_; lv++) loss = __fadd_rn(loss, means[lv]);
        out[0] = loss;
    }
}

// ---------------- launcher -------------------------------------------------------
extern "C" void kernel_launch(void* const* d_in, const int* in_sizes, int n_in,
                              void* d_out, int out_size) {
    const float* z  = (const float*)d_in[0];   // [B, D]
    const float* cb = (const float*)d_in[1];   // [L, K, D]
    float* out = (float*)d_out;
    float* outq  = out;
    float* outlv = out + (size_t)B_ * D_;
    float* outls = out + (size_t)B_ * D_ * (size_t)(1 + L_);

    static bool attr_set = false;
    if (!attr_set) {
        cudaFuncSetAttribute(gemm_kernel,
                             cudaFuncAttributeMaxDynamicSharedMemorySize, SM_TOTAL);
        attr_set = true;
    }

    convc2_kernel<<<(L_ * K_ * 32) / 256, 256>>>(cb);

    for (int l = 0; l < L_; l++) {
        gemm_kernel<<<B_ / 64, 256, SM_TOTAL>>>(z, l);
        argmin_update_kernel<<<B_ / 8, 256>>>(z, cb, outlv, outq, l);
    }

    loss_kernel<<<1, 1024>>>(outls);
}

// round 16
// speedup vs baseline: 1.2106x; 1.2106x over previous
#include <cuda_runtime.h>
#include <cuda_bf16.h>
#include <cfloat>
#include <climits>
#include <cstdint>

// Problem constants
#define B_ 32768
#define D_ 512
#define L_ 4
#define K_ 1024

// Candidate margin (score units). Screened-score error is bf16-GEMM noise only
// (sigma ~0.014); 0.15 ~ 10 sigma. Single final candidate => provably the
// reference argmin; otherwise tiered exact rescore.
#define MARGIN 0.15f
#define MAXCAND 12
// fp32-tier ambiguity guard: pairwise |S_f32 - S_ref| bound ~2.5e-4; 6e-4 is
// comfortably above it, so fp32 gap >= guard proves the reference ordering.
#define FP32_GUARD 6e-4f

// ---------------- scratch (__device__ globals; no allocations allowed) -----------
__device__ float          g_residual[(size_t)B_ * D_];   // fp32 residual, 64 MB
__device__ __nv_bfloat16  g_rb[(size_t)B_ * D_];         // bf16 residual (GEMM A), 32 MB
__device__ __nv_bfloat16  g_cbh[(size_t)L_ * K_ * D_];   // bf16 codebooks, 4 MB
__device__ float          g_c2[L_ * K_];
__device__ int            g_ccnt[B_];
__device__ int            g_cand[B_][MAXCAND];
__device__ float          g_rowss[L_ * B_];

__device__ __forceinline__ uint32_t smem_u32(const void* p) {
    uint32_t a;
    asm("{ .reg .u64 t; cvta.to.shared.u64 t, %1; cvt.u32.u64 %0, t; }" : "=r"(a) : "l"(p));
    return a;
}
// order-preserving float <-> uint map (atomicMin on scores, incl. negatives)
__device__ __forceinline__ unsigned fkey(float f) {
    unsigned u = __float_as_uint(f);
    return (u & 0x80000000u) ? ~u : (u | 0x80000000u);
}
__device__ __forceinline__ float fdec(unsigned k) {
    unsigned u = (k & 0x80000000u) ? (k ^ 0x80000000u) : ~k;
    return __uint_as_float(u);
}

// ---------------- fused codebook prep: bf16 convert + ||c||^2 --------------------
// One warp per codeword: single 8 MB read serves both outputs.
// c2 fp64-accumulated -> correctly-rounded fp32 (order-independent at fp32).
__global__ void convc2_kernel(const float* __restrict__ cb) {
    int g = blockIdx.x * blockDim.x + threadIdx.x;
    int w = g >> 5, lane = g & 31;
    const float* row = cb + (size_t)w * D_;
    float4 v[4];
    #pragma unroll
    for (int q = 0; q < 4; q++)
        v[q] = reinterpret_cast<const float4*>(row)[lane * 4 + q];
    double s = 0.0;
    __nv_bfloat162 h[8];
    #pragma unroll
    for (int q = 0; q < 4; q++) {
        h[q * 2 + 0] = __floats2bfloat162_rn(v[q].x, v[q].y);
        h[q * 2 + 1] = __floats2bfloat162_rn(v[q].z, v[q].w);
        s = fma((double)v[q].x, (double)v[q].x, s);
        s = fma((double)v[q].y, (double)v[q].y, s);
        s = fma((double)v[q].z, (double)v[q].z, s);
        s = fma((double)v[q].w, (double)v[q].w, s);
    }
    __nv_bfloat16* dst = g_cbh + (size_t)w * D_ + lane * 16;
    *reinterpret_cast<uint4*>(dst)     = *reinterpret_cast<uint4*>(&h[0]);
    *reinterpret_cast<uint4*>(dst + 8) = *reinterpret_cast<uint4*>(&h[4]);
    #pragma unroll
    for (int o = 16; o; o >>= 1) s += __shfl_xor_sync(0xffffffffu, s, o);
    if (!lane) g_c2[w] = (float)s;
}

// ---------------- bf16 MMA GEMM + fused min/candidate epilogue -------------------
// Per CTA: 64 rows x all 1024 codes, K=512. 256 threads, warp tile 32x32.
// 2-buffer B pipeline, 96 KB smem/CTA => 2 CTA/SM (PROVEN config; 3-stage
// pipeline exceeds the 228 KB carveout at 2 CTA/SM and drops occupancy).
// Level 0 stages A directly from z (inline fp32->bf16 convert).
#define SM_A     0
#define SM_B     65536
#define SM_BBUF  16384
#define SM_TOTAL (65536 + 2 * 16384)

__device__ __forceinline__ void ldsm_x4(uint32_t* r, uint32_t addr) {
    asm volatile("ldmatrix.sync.aligned.m8n8.x4.shared.b16 {%0,%1,%2,%3}, [%4];"
        : "=r"(r[0]), "=r"(r[1]), "=r"(r[2]), "=r"(r[3]) : "r"(addr));
}
__device__ __forceinline__ void mma16816(float* c, const uint32_t* a, uint32_t b0, uint32_t b1) {
    asm volatile("mma.sync.aligned.m16n8k16.row.col.f32.bf16.bf16.f32 "
        "{%0,%1,%2,%3}, {%4,%5,%6,%7}, {%8,%9}, {%0,%1,%2,%3};"
        : "+f"(c[0]), "+f"(c[1]), "+f"(c[2]), "+f"(c[3])
        : "r"(a[0]), "r"(a[1]), "r"(a[2]), "r"(a[3]), "r"(b0), "r"(b1));
}

__global__ __launch_bounds__(256, 2) void gemm_kernel(const float* __restrict__ z, int level) {
    extern __shared__ char smem[];
    __shared__ unsigned bestKey[64];
    __shared__ int   ccnt[64];
    __shared__ int   candI[64][MAXCAND];
    __shared__ float candS[64][MAXCAND];

    const int tid = threadIdx.x, wid = tid >> 5, lane = tid & 31;
    const int m0 = blockIdx.x * 64;
    const __nv_bfloat16* Bsrc = g_cbh + (size_t)level * K_ * D_;
    const float* c2l = g_c2 + level * K_;
    const uint32_t sb = smem_u32(smem);

    if (tid < 64) { bestKey[tid] = 0xFFFFFFFFu; ccnt[tid] = 0; }

    // Stage A: 64 rows x 512 bf16, XOR-swizzled 16B chunks.
    if (level == 0) {
        // Read z directly, convert inline (no g_rb round-trip for level 0).
        #pragma unroll
        for (int i = 0; i < 16; i++) {
            int q = tid + i * 256;
            int m = q >> 6, c = q & 63;
            const float* zp = z + (size_t)(m0 + m) * D_ + c * 8;
            float4 a = *reinterpret_cast<const float4*>(zp);
            float4 b = *reinterpret_cast<const float4*>(zp + 4);
            __nv_bfloat162 h[4] = { __floats2bfloat162_rn(a.x, a.y),
                                    __floats2bfloat162_rn(a.z, a.w),
                                    __floats2bfloat162_rn(b.x, b.y),
                                    __floats2bfloat162_rn(b.z, b.w) };
            *reinterpret_cast<uint4*>(smem + SM_A + m * 1024 + ((c ^ (m & 7)) * 16)) =
                *reinterpret_cast<uint4*>(h);
        }
    } else {
        #pragma unroll
        for (int i = 0; i < 16; i++) {
            int q = tid + i * 256;
            int m = q >> 6, c = q & 63;
            uint32_t dst = sb + SM_A + m * 1024 + ((c ^ (m & 7)) * 16);
            const void* g = g_rb + (size_t)(m0 + m) * D_ + c * 8;
            asm volatile("cp.async.cg.shared.global [%0], [%1], 16;" :: "r"(dst), "l"(g));
        }
        asm volatile("cp.async.commit_group;");
    }

    // B chunk ci in 0..63: nt = ci>>3 (128-col tile), kc = ci&7 (64-k slab).
    #define LOAD_B_CHUNK(ci, buf) do {                                               \
        int _nt = (ci) >> 3, _kc = (ci) & 7;                                         \
        const __nv_bfloat16* _src = Bsrc + (size_t)(_nt * 128) * D_ + _kc * 64;      \
        _Pragma("unroll")                                                            \
        for (int _i = 0; _i < 4; _i++) {                                             \
            int _q = tid + _i * 256;                                                 \
            int _n = _q >> 3, _c = _q & 7;                                           \
            uint32_t _dst = sb + SM_B + (buf) * SM_BBUF + _n * 128 +                 \
                            ((_c ^ (_n & 7)) * 16);                                  \
            const void* _g = _src + (size_t)_n * D_ + _c * 8;                        \
            asm volatile("cp.async.cg.shared.global [%0], [%1], 16;"                 \
                         :: "r"(_dst), "l"(_g));                                     \
        }                                                                            \
        asm volatile("cp.async.commit_group;");                                      \
    } while (0)

    const int wm = wid & 1, wn = wid >> 1;   // warp tile: rows wm*32..+31, cols wn*32..+31
    const int lr = lane & 7;
    const int lh = (lane >> 3) & 1;
    const int lk = lane >> 4;

    LOAD_B_CHUNK(0, 0);

    float acc[2][4][4];

    for (int ci = 0; ci < 64; ci++) {
        const int buf = ci & 1;
        asm volatile("cp.async.wait_group 0;");
        __syncthreads();
        if (ci + 1 < 64) LOAD_B_CHUNK(ci + 1, buf ^ 1);

        const int nt = ci >> 3, kc = ci & 7;

        if (kc == 0) {
            #pragma unroll
            for (int mt = 0; mt < 2; mt++)
                #pragma unroll
                for (int nti = 0; nti < 4; nti++)
                    #pragma unroll
                    for (int q = 0; q < 4; q++) acc[mt][nti][q] = 0.f;
        }

        #pragma unroll
        for (int ks = 0; ks < 4; ks++) {
            uint32_t a[2][4];
            #pragma unroll
            for (int mt = 0; mt < 2; mt++) {
                int m = wm * 32 + mt * 16 + lh * 8 + lr;
                int ch = kc * 8 + ks * 2 + lk;
                uint32_t addr = sb + SM_A + m * 1024 + ((ch ^ (m & 7)) * 16);
                ldsm_x4(a[mt], addr);
            }
            uint32_t b[2][4];
            #pragma unroll
            for (int p = 0; p < 2; p++) {
                int n = wn * 32 + p * 16 + lk * 8 + lr;
                int ch = ks * 2 + lh;
                uint32_t addr = sb + SM_B + buf * SM_BBUF + n * 128 + ((ch ^ (n & 7)) * 16);
                ldsm_x4(b[p], addr);
            }
            #pragma unroll
            for (int mt = 0; mt < 2; mt++)
                #pragma unroll
                for (int nti = 0; nti < 4; nti++)
                    mma16816(acc[mt][nti], a[mt],
                             b[nti >> 1][(nti & 1) * 2 + 0],
                             b[nti >> 1][(nti & 1) * 2 + 1]);
        }

        if (kc == 7) {
            // ---- epilogue for this 128-col tile ----
            // pass 1: per-row running min (ordered-uint atomicMin)
            #pragma unroll
            for (int mt = 0; mt < 2; mt++) {
                #pragma unroll
                for (int h = 0; h < 2; h++) {
                    int row = wm * 32 + mt * 16 + h * 8 + (lane >> 2);
                    float lmin = FLT_MAX;
                    #pragma unroll
                    for (int nti = 0; nti < 4; nti++) {
                        int col = nt * 128 + wn * 32 + nti * 8 + (lane & 3) * 2;
                        float2 cv = *reinterpret_cast<const float2*>(c2l + col);
                        float s0 = fmaf(-2.f, acc[mt][nti][h * 2 + 0], cv.x);
                        float s1 = fmaf(-2.f, acc[mt][nti][h * 2 + 1], cv.y);
                        lmin = fminf(lmin, fminf(s0, s1));
                    }
                    atomicMin(&bestKey[row], fkey(lmin));
                }
            }
            __syncthreads();
            // pass 2: candidates vs (running min + MARGIN) [superset of final set]
            #pragma unroll
            for (int mt = 0; mt < 2; mt++) {
                #pragma unroll
                for (int h = 0; h < 2; h++) {
                    int row = wm * 32 + mt * 16 + h * 8 + (lane >> 2);
                    float thr = fdec(bestKey[row]) + MARGIN;
                    #pragma unroll
                    for (int nti = 0; nti < 4; nti++) {
                        int col = nt * 128 + wn * 32 + nti * 8 + (lane & 3) * 2;
                        float2 cv = *reinterpret_cast<const float2*>(c2l + col);
                        float s0 = fmaf(-2.f, acc[mt][nti][h * 2 + 0], cv.x);
                        float s1 = fmaf(-2.f, acc[mt][nti][h * 2 + 1], cv.y);
                        if (s0 <= thr) {
                            int p = atomicAdd(&ccnt[row], 1);
                            if (p < MAXCAND) { candI[row][p] = col; candS[row][p] = s0; }
                        }
                        if (s1 <= thr) {
                            int p = atomicAdd(&ccnt[row], 1);
                            if (p < MAXCAND) { candI[row][p] = col + 1; candS[row][p] = s1; }
                        }
                    }
                }
            }
        }
    }
    #undef LOAD_B_CHUNK
    __syncthreads();

    // Final per-row filter & writeout (one thread per row).
    if (tid < 64) {
        int b = m0 + tid;
        int c = ccnt[tid];
        if (c > MAXCAND) {
            g_ccnt[b] = 999;                       // overflow: full rescan in resolve
        } else {
            float thr = fdec(bestKey[tid]) + MARGIN;
            int m = 0;
            for (int i = 0; i < c; i++)
                if (candS[tid][i] <= thr) g_cand[b][m++] = candI[tid][i];
            g_ccnt[b] = m;                          // m >= 1 always (min itself)
        }
    }
}

// ---------------- candidate resolve + tiered exact rescore + update --------------
// One warp per row (fused — proven faster than split at this kernel size).
// n==1 => provably correct winner. Else tier-1: fp32 exact-input rescore; if
// its top-2 gap >= FP32_GUARD the winner provably matches the reference
// argmin. Residue -> tier-2: fp64 dot + the reference's fp32 rounding chain
// (lowest-index ties). Then residual update, level vec, bf16 mirror (levels
// 0-2), per-row sumsq, and at level 3 quantized = z - residual.
__global__ __launch_bounds__(256) void argmin_update_kernel(const float* __restrict__ z,
                                                            const float* __restrict__ cb,
                                                            float* __restrict__ lv_base,
                                                            float* __restrict__ outq,
                                                            int level) {
    const int tid = threadIdx.x, wid = tid >> 5, lane = tid & 31;
    const int b = blockIdx.x * 8 + wid;
    const float* prevres = level ? g_residual : z;
    const float* rrow = prevres + (size_t)b * D_;
    const float* cbl = cb + (size_t)level * K_ * D_;
    const float* c2l = g_c2 + level * K_;

    int n = g_ccnt[b];
    int idx;
    if (n == 1) {
        idx = g_cand[b][0];
    } else {
        float rres[16];
        #pragma unroll
        for (int j = 0; j < 16; j++) rres[j] = rrow[j * 32 + lane];
        const bool full = (n > MAXCAND);
        const int cnt = full ? K_ : n;

        // ---- tier 1: fp32 exact-input rescore, track top-2 ----
        float bestS = FLT_MAX, secondS = FLT_MAX; int bi = INT_MAX;
        for (int t = 0; t < cnt; t++) {
            int k = full ? t : g_cand[b][t];
            const float* crow = cbl + (size_t)k * D_;
            float dp0 = 0.f, dp1 = 0.f;
            #pragma unroll
            for (int j = 0; j < 16; j += 2) {
                dp0 = fmaf(rres[j],     crow[j * 32 + lane],       dp0);
                dp1 = fmaf(rres[j + 1], crow[(j + 1) * 32 + lane], dp1);
            }
            float dp = dp0 + dp1;
            #pragma unroll
            for (int o = 16; o; o >>= 1) dp += __shfl_xor_sync(0xffffffffu, dp, o);
            float S = fmaf(-2.f, dp, __ldg(c2l + k));
            if (S < bestS || (S == bestS && k < bi)) {
                secondS = bestS; bestS = S; bi = k;
            } else if (S < secondS) {
                secondS = S;
            }
        }
        idx = bi;

        // ---- tier 2: ambiguous -> fp64 + reference fp32 rounding chain ----
        if (secondS - bestS < FP32_GUARD) {
            double rd[16]; double r2 = 0.0;
            #pragma unroll
            for (int j = 0; j < 16; j++) {
                double v = (double)rres[j];
                rd[j] = v; r2 = fma(v, v, r2);
            }
            #pragma unroll
            for (int o = 16; o; o >>= 1) r2 += __shfl_xor_sync(0xffffffffu, r2, o);
            float r2f = (float)r2;

            float bS = FLT_MAX; int bk = INT_MAX;
            for (int t = 0; t < cnt; t++) {
                int k = full ? t : g_cand[b][t];
                const float* crow = cbl + (size_t)k * D_;
                double dp0 = 0.0, dp1 = 0.0;
                #pragma unroll
                for (int j = 0; j < 16; j += 2) {
                    dp0 = fma(rd[j],     (double)crow[j * 32 + lane],       dp0);
                    dp1 = fma(rd[j + 1], (double)crow[(j + 1) * 32 + lane], dp1);
                }
                double dp = dp0 + dp1;
                #pragma unroll
                for (int o = 16; o; o >>= 1) dp += __shfl_xor_sync(0xffffffffu, dp, o);
                float S = __fadd_rn(__fsub_rn(r2f, __fmul_rn(2.0f, (float)dp)),
                                    __ldg(c2l + k));
                if (S < bS || (S == bS && k < bk)) { bS = S; bk = k; }
            }
            idx = bk;
        }
    }

    // ---- update phase ----
    const float4* c  = reinterpret_cast<const float4*>(cbl + (size_t)idx * D_);
    const float4* r  = reinterpret_cast<const float4*>(rrow);
    float4* ro = reinterpret_cast<float4*>(g_residual + (size_t)b * D_);
    float4* lo = reinterpret_cast<float4*>(lv_base + (size_t)level * B_ * D_ + (size_t)b * D_);
    const float4* zv = reinterpret_cast<const float4*>(z + (size_t)b * D_);
    float4* oq = reinterpret_cast<float4*>(outq + (size_t)b * D_);
    float ss = 0.f;
    #pragma unroll
    for (int d = lane; d < D_ / 4; d += 32) {
        float4 rv = r[d], cv = c[d];
        float4 nv = make_float4(rv.x - cv.x, rv.y - cv.y, rv.z - cv.z, rv.w - cv.w);
        lo[d] = cv;
        if (level < 3) {
            ro[d] = nv;
            __nv_bfloat162 h0 = __floats2bfloat162_rn(nv.x, nv.y);
            __nv_bfloat162 h1 = __floats2bfloat162_rn(nv.z, nv.w);
            uint2 pk = make_uint2(*reinterpret_cast<uint32_t*>(&h0),
                                  *reinterpret_cast<uint32_t*>(&h1));
            *reinterpret_cast<uint2*>(g_rb + (size_t)b * D_ + d * 4) = pk;
        } else {
            float4 zq = zv[d];
            oq[d] = make_float4(zq.x - nv.x, zq.y - nv.y, zq.z - nv.z, zq.w - nv.w);
        }
        ss = fmaf(nv.x, nv.x, fmaf(nv.y, nv.y, fmaf(nv.z, nv.z, fmaf(nv.w, nv.w, ss))));
    }
    #pragma unroll
    for (int o = 16; o; o >>= 1) ss += __shfl_xor_sync(0xffffffffu, ss, o);
    if (!lane) g_rowss[level * B_ + b] = ss;
}

// ---------------- loss: levels reduced in parallel (deterministic tree) ----------
__global__ __launch_bounds__(1024) void loss_kernel(float* __restrict__ out) {
    __shared__ double sh[1024];
    __shared__ float means[L_];
    const int t = threadIdx.x;
    const int l = t >> 8, u = t & 255;
    double s = 0.0;
    #pragma unroll 8
    for (int i = u; i < B_; i += 256) s += (double)g_rowss[l * B_ + i];
    sh[t] = s; __syncthreads();
    for (int o = 128; o; o >>= 1) {
        if (u < o) sh[t] += sh[t + o];
        __syncthreads();
    }
    if (u == 0) means[l] = (float)(sh[t] / ((double)B_ * (double)D_));
    __syncthreads();
    if (t == 0) {
        float loss = 0.f;
        for (int lv = 0; lv < L_; lv++) loss = __fadd_rn(loss, means[lv]);
        out[0] = loss;
    }
}

// ---------------- launcher -------------------------------------------------------
extern "C" void kernel_launch(void* const* d_in, const int* in_sizes, int n_in,
                              void* d_out, int out_size) {
    const float* z  = (const float*)d_in[0];   // [B, D]
    const float* cb = (const float*)d_in[1];   // [L, K, D]
    float* out = (float*)d_out;
    float* outq  = out;
    float* outlv = out + (size_t)B_ * D_;
    float* outls = out + (size_t)B_ * D_ * (size_t)(1 + L_);

    static bool attr_set = false;
    if (!attr_set) {
        cudaFuncSetAttribute(gemm_kernel,
                             cudaFuncAttributeMaxDynamicSharedMemorySize, SM_TOTAL);
        attr_set = true;
    }

    convc2_kernel<<<(L_ * K_ * 32) / 256, 256>>>(cb);

    for (int l = 0; l < L_; l++) {
        gemm_kernel<<<B_ / 64, 256, SM_TOTAL>>>(z, l);
        argmin_update_kernel<<<B_ / 8, 256>>>(z, cb, outlv, outq, l);
    }

    loss_kernel<<<1, 1024>>>(outls);
}